// round 1
// baseline (speedup 1.0000x reference)
#include <cuda_runtime.h>

// DeepSets: out[s,f] = (sum_{i in seg s} x[i,0])*W[0,f] + (sum x[i,1])*W[1,f] + cnt_s*b[f]
// Exploits linearity: segment_sum(xW+b) == segment_sum(x) W + cnt*b.
// segment_ids are sorted -> per-segment contiguous range found by binary search.

#define FEAT_OUT 64
#define BLOCK_THREADS 256

__global__ __launch_bounds__(BLOCK_THREADS)
void deepsets_seg_kernel(const float2* __restrict__ x,
                         const int* __restrict__ ids,
                         const float* __restrict__ W,   // [2,64] row-major
                         const float* __restrict__ b,   // [64]
                         float* __restrict__ out,       // [num_segments,64]
                         int N)
{
    const int s = blockIdx.x;
    __shared__ int bounds[2];

    // Two threads do the two lower_bound searches.
    if (threadIdx.x < 2) {
        const int target = s + (int)threadIdx.x;
        int lo = 0, hi = N;
        while (lo < hi) {
            int mid = (lo + hi) >> 1;
            if (__ldg(&ids[mid]) < target) lo = mid + 1; else hi = mid;
        }
        bounds[threadIdx.x] = lo;
    }
    __syncthreads();

    const int start = bounds[0];
    const int end   = bounds[1];
    const int cnt   = end - start;

    // Coalesced streaming sum of this segment's points.
    float sx = 0.0f, sy = 0.0f;
    for (int i = start + (int)threadIdx.x; i < end; i += BLOCK_THREADS) {
        float2 p = __ldg(&x[i]);
        sx += p.x;
        sy += p.y;
    }

    // Warp reduction
    #pragma unroll
    for (int o = 16; o > 0; o >>= 1) {
        sx += __shfl_down_sync(0xFFFFFFFFu, sx, o);
        sy += __shfl_down_sync(0xFFFFFFFFu, sy, o);
    }

    __shared__ float wsx[BLOCK_THREADS / 32];
    __shared__ float wsy[BLOCK_THREADS / 32];
    const int warp = threadIdx.x >> 5;
    const int lane = threadIdx.x & 31;
    if (lane == 0) { wsx[warp] = sx; wsy[warp] = sy; }
    __syncthreads();

    // First 64 threads each compute one output feature.
    if (threadIdx.x < FEAT_OUT) {
        float SX = 0.0f, SY = 0.0f;
        #pragma unroll
        for (int w = 0; w < BLOCK_THREADS / 32; w++) {
            SX += wsx[w];
            SY += wsy[w];
        }
        const int f = threadIdx.x;
        const float w0 = __ldg(&W[f]);
        const float w1 = __ldg(&W[FEAT_OUT + f]);
        const float bf = __ldg(&b[f]);
        out[(size_t)s * FEAT_OUT + f] = fmaf(SX, w0, fmaf(SY, w1, (float)cnt * bf));
    }
}

extern "C" void kernel_launch(void* const* d_in, const int* in_sizes, int n_in,
                              void* d_out, int out_size)
{
    const float2* x  = (const float2*)d_in[0];        // [N,2] float32
    const int*   ids = (const int*)d_in[1];           // [N] int32, sorted
    const float* W   = (const float*)d_in[2];         // [2,64]
    const float* b   = (const float*)d_in[3];         // [64]
    float* out = (float*)d_out;

    const int N = in_sizes[0] / 2;                    // in_sizes[0] = N*2 elements
    const int num_segments = out_size / FEAT_OUT;     // 4096

    deepsets_seg_kernel<<<num_segments, BLOCK_THREADS>>>(x, ids, W, b, out, N);
}

// round 2
// speedup vs baseline: 1.5233x; 1.5233x over previous
#include <cuda_runtime.h>

// DeepSets: out[s,f] = sx_s*W[0,f] + sy_s*W[1,f] + cnt_s*b[f]
// (linearity: segment_sum(xW+b) == segment_sum(x)@W + cnt*b)
//
// Kernel 1: warp-wide 32-ary lower_bound for each of the 4097 segment
//           boundaries -> g_offsets (kills the serial binary-search chain).
// Kernel 2: one CTA per segment streams its contiguous x range (coalesced),
//           block-reduces (sx, sy), writes 64 output features.

#define FEAT_OUT 64
#define MAX_SEGMENTS 4096
#define BLOCK_THREADS 256

__device__ int g_offsets[MAX_SEGMENTS + 1];

// ---------------------------------------------------------------------------
// Kernel 1: one warp per boundary target t in [0, num_segments], computes
// lower_bound(ids, t) with a 33-way narrowing per round (5-6 rounds total).
// ---------------------------------------------------------------------------
__global__ __launch_bounds__(128)
void find_offsets_kernel(const int* __restrict__ ids, int N, int num_segments)
{
    const int warp_in_blk = threadIdx.x >> 5;
    const int lane        = threadIdx.x & 31;
    const int target      = blockIdx.x * 4 + warp_in_blk;   // 0..num_segments
    if (target > num_segments) return;

    int lo = 0, hi = N;   // invariant: answer in [lo, hi]
    while (hi > lo) {
        const int m = hi - lo;
        // probe position for this lane; p in [lo, hi)
        const int p = lo + (int)(((long long)m * (lane + 1)) / 33);
        const int v = __ldg(&ids[p]);
        const unsigned pred = __ballot_sync(0xFFFFFFFFu, v < target);
        const int c = __popc(pred);   // # probes with ids[p] < target (prefix, monotone)
        // new bounds
        int new_lo, new_hi;
        if (c == 0) {
            new_lo = lo;
        } else {
            const int p_last_true = lo + (int)(((long long)m * c) / 33); // p_{c-1}
            new_lo = p_last_true + 1;
        }
        if (c == 32) {
            new_hi = hi;
        } else {
            const int p_first_false = lo + (int)(((long long)m * (c + 1)) / 33); // p_c
            new_hi = p_first_false;
        }
        lo = new_lo;
        hi = new_hi;
    }
    if (lane == 0) g_offsets[target] = lo;
}

// ---------------------------------------------------------------------------
// Kernel 2: one CTA per segment; pure coalesced streaming + reduction.
// ---------------------------------------------------------------------------
__global__ __launch_bounds__(BLOCK_THREADS)
void segment_stream_kernel(const float2* __restrict__ x,
                           const float* __restrict__ W,   // [2,64]
                           const float* __restrict__ b,   // [64]
                           float* __restrict__ out)       // [num_segments,64]
{
    const int s     = blockIdx.x;
    const int start = g_offsets[s];
    const int end   = g_offsets[s + 1];
    const int cnt   = end - start;

    float sx = 0.0f, sy = 0.0f;
    for (int i = start + (int)threadIdx.x; i < end; i += BLOCK_THREADS) {
        float2 p = __ldg(&x[i]);
        sx += p.x;
        sy += p.y;
    }

    #pragma unroll
    for (int o = 16; o > 0; o >>= 1) {
        sx += __shfl_down_sync(0xFFFFFFFFu, sx, o);
        sy += __shfl_down_sync(0xFFFFFFFFu, sy, o);
    }

    __shared__ float wsx[BLOCK_THREADS / 32];
    __shared__ float wsy[BLOCK_THREADS / 32];
    const int warp = threadIdx.x >> 5;
    const int lane = threadIdx.x & 31;
    if (lane == 0) { wsx[warp] = sx; wsy[warp] = sy; }
    __syncthreads();

    if (threadIdx.x < FEAT_OUT) {
        float SX = 0.0f, SY = 0.0f;
        #pragma unroll
        for (int w = 0; w < BLOCK_THREADS / 32; w++) {
            SX += wsx[w];
            SY += wsy[w];
        }
        const int f = threadIdx.x;
        const float w0 = __ldg(&W[f]);
        const float w1 = __ldg(&W[FEAT_OUT + f]);
        const float bf = __ldg(&b[f]);
        out[(size_t)s * FEAT_OUT + f] = fmaf(SX, w0, fmaf(SY, w1, (float)cnt * bf));
    }
}

extern "C" void kernel_launch(void* const* d_in, const int* in_sizes, int n_in,
                              void* d_out, int out_size)
{
    const float2* x  = (const float2*)d_in[0];   // [N,2] float32
    const int*   ids = (const int*)d_in[1];      // [N] int32, sorted
    const float* W   = (const float*)d_in[2];    // [2,64]
    const float* b   = (const float*)d_in[3];    // [64]
    float* out = (float*)d_out;

    const int N = in_sizes[0] / 2;
    const int num_segments = out_size / FEAT_OUT;   // 4096

    // 4 warps per block, one warp per boundary (num_segments+1 boundaries)
    const int nb = (num_segments + 1 + 3) / 4;
    find_offsets_kernel<<<nb, 128>>>(ids, N, num_segments);
    segment_stream_kernel<<<num_segments, BLOCK_THREADS>>>(x, W, b, out);
}

// round 3
// speedup vs baseline: 1.7975x; 1.1800x over previous
#include <cuda_runtime.h>

// DeepSets: out[s,f] = sx_s*W[0,f] + sy_s*W[1,f] + cnt_s*b[f]
// (linearity: segment_sum(xW+b) == segment_sum(x)@W + cnt*b)
//
// Kernel 1: warp-wide 32-ary lower_bound per boundary -> g_offsets.
// Kernel 2: one CTA (128 thr) per segment; float4 body with 4-wide
//           independent-load unroll for MLP, scalar head/tail for alignment.

#define FEAT_OUT 64
#define MAX_SEGMENTS 4096
#define BLOCK 128

__device__ int g_offsets[MAX_SEGMENTS + 1];

// ---------------------------------------------------------------------------
// Kernel 1: one warp per boundary target t in [0, num_segments].
// ---------------------------------------------------------------------------
__global__ __launch_bounds__(128)
void find_offsets_kernel(const int* __restrict__ ids, int N, int num_segments)
{
    const int warp_in_blk = threadIdx.x >> 5;
    const int lane        = threadIdx.x & 31;
    const int target      = blockIdx.x * 4 + warp_in_blk;
    if (target > num_segments) return;

    int lo = 0, hi = N;
    while (hi > lo) {
        const int m = hi - lo;
        const int p = lo + (int)(((long long)m * (lane + 1)) / 33);
        const int v = __ldg(&ids[p]);
        const unsigned pred = __ballot_sync(0xFFFFFFFFu, v < target);
        const int c = __popc(pred);
        int new_lo, new_hi;
        if (c == 0) new_lo = lo;
        else        new_lo = lo + (int)(((long long)m * c) / 33) + 1;
        if (c == 32) new_hi = hi;
        else         new_hi = lo + (int)(((long long)m * (c + 1)) / 33);
        lo = new_lo;
        hi = new_hi;
    }
    if (lane == 0) g_offsets[target] = lo;
}

// ---------------------------------------------------------------------------
// Kernel 2: one CTA per segment; MLP-4 float4 streaming.
// ---------------------------------------------------------------------------
__global__ __launch_bounds__(BLOCK)
void segment_stream_kernel(const float2* __restrict__ x,
                           const float* __restrict__ W,   // [2,64]
                           const float* __restrict__ b,   // [64]
                           float* __restrict__ out)       // [num_segments,64]
{
    const int s     = blockIdx.x;
    const int start = g_offsets[s];
    const int end   = g_offsets[s + 1];
    const int cnt   = end - start;

    float sx = 0.0f, sy = 0.0f;

    // Head: if start is odd, point `start` handled by thread 0.
    if ((start & 1) && start < end) {
        if (threadIdx.x == 0) {
            float2 p = __ldg(&x[start]);
            sx += p.x; sy += p.y;
        }
    }

    const int astart = (start + 1) & ~1;            // first pair-aligned point
    const int span   = end - astart;                // may be negative if cnt==0
    const int pairs  = span >> 1;                   // float4 count (floor)
    const float4* __restrict__ xb = reinterpret_cast<const float4*>(x + astart);

    // Body: 4 independent predicated loads per iteration (MLP=4).
    for (int j = (int)threadIdx.x; j < pairs; j += 4 * BLOCK) {
        const int j1 = j + BLOCK, j2 = j + 2 * BLOCK, j3 = j + 3 * BLOCK;
        float4 v0 = __ldg(&xb[j]);
        float4 v1 = make_float4(0.f, 0.f, 0.f, 0.f);
        float4 v2 = make_float4(0.f, 0.f, 0.f, 0.f);
        float4 v3 = make_float4(0.f, 0.f, 0.f, 0.f);
        if (j1 < pairs) v1 = __ldg(&xb[j1]);
        if (j2 < pairs) v2 = __ldg(&xb[j2]);
        if (j3 < pairs) v3 = __ldg(&xb[j3]);
        sx += (v0.x + v0.z) + (v1.x + v1.z) + (v2.x + v2.z) + (v3.x + v3.z);
        sy += (v0.y + v0.w) + (v1.y + v1.w) + (v2.y + v2.w) + (v3.y + v3.w);
    }

    // Tail: leftover odd point at end-1.
    if (span > 0 && (span & 1)) {
        if (threadIdx.x == (BLOCK - 1)) {
            float2 p = __ldg(&x[end - 1]);
            sx += p.x; sy += p.y;
        }
    }

    // Hoist epilogue operand loads to overlap with the reduction.
    float w0 = 0.f, w1 = 0.f, bf = 0.f;
    if (threadIdx.x < FEAT_OUT) {
        const int f = threadIdx.x;
        w0 = __ldg(&W[f]);
        w1 = __ldg(&W[FEAT_OUT + f]);
        bf = __ldg(&b[f]);
    }

    // Warp reduction
    #pragma unroll
    for (int o = 16; o > 0; o >>= 1) {
        sx += __shfl_down_sync(0xFFFFFFFFu, sx, o);
        sy += __shfl_down_sync(0xFFFFFFFFu, sy, o);
    }

    __shared__ float wsx[BLOCK / 32];
    __shared__ float wsy[BLOCK / 32];
    const int warp = threadIdx.x >> 5;
    const int lane = threadIdx.x & 31;
    if (lane == 0) { wsx[warp] = sx; wsy[warp] = sy; }
    __syncthreads();

    if (threadIdx.x < FEAT_OUT) {
        float SX = 0.0f, SY = 0.0f;
        #pragma unroll
        for (int w = 0; w < BLOCK / 32; w++) {
            SX += wsx[w];
            SY += wsy[w];
        }
        const int f = threadIdx.x;
        out[(size_t)s * FEAT_OUT + f] = fmaf(SX, w0, fmaf(SY, w1, (float)cnt * bf));
    }
}

extern "C" void kernel_launch(void* const* d_in, const int* in_sizes, int n_in,
                              void* d_out, int out_size)
{
    const float2* x  = (const float2*)d_in[0];   // [N,2] float32
    const int*   ids = (const int*)d_in[1];      // [N] int32, sorted
    const float* W   = (const float*)d_in[2];    // [2,64]
    const float* b   = (const float*)d_in[3];    // [64]
    float* out = (float*)d_out;

    const int N = in_sizes[0] / 2;
    const int num_segments = out_size / FEAT_OUT;   // 4096

    const int nb = (num_segments + 1 + 3) / 4;
    find_offsets_kernel<<<nb, 128>>>(ids, N, num_segments);
    segment_stream_kernel<<<num_segments, BLOCK>>>(x, W, b, out);
}